// round 13
// baseline (speedup 1.0000x reference)
#include <cuda_runtime.h>
#include <math.h>

// RoPE-2D: x[B=32, S=1024, H=16, D=64] fp32, grid_sizes[B,2] int32.
// Combined rotation: rot(i*th) ∘ rot(j*th) == rot((i+j)*th).
//
// Config: block=64 covers ONE s-row (4 KB). Each thread moves 64 B via
// two 256-bit ld/st.global.v8.f32 (sm_103a) — half the LDG/STG issue
// slots and L1tex wavefront entries of the float4 version. The thread's
// two float8s (tid, tid+64) share pos AND pair-group (same d-offset,
// different head) -> only 4 sincos/thread. Streaming .cs on both paths.

#define S_LOG2 10

__device__ __forceinline__ void ldg256_cs(const float* p, float* r) {
    asm volatile("ld.global.cs.v8.f32 {%0,%1,%2,%3,%4,%5,%6,%7}, [%8];"
                 : "=f"(r[0]), "=f"(r[1]), "=f"(r[2]), "=f"(r[3]),
                   "=f"(r[4]), "=f"(r[5]), "=f"(r[6]), "=f"(r[7])
                 : "l"(p));
}

__device__ __forceinline__ void stg256_cs(float* p, const float* r) {
    asm volatile("st.global.cs.v8.f32 [%0], {%1,%2,%3,%4,%5,%6,%7,%8};"
                 :: "l"(p),
                    "f"(r[0]), "f"(r[1]), "f"(r[2]), "f"(r[3]),
                    "f"(r[4]), "f"(r[5]), "f"(r[6]), "f"(r[7])
                 : "memory");
}

__global__ void __launch_bounds__(64) rope2d_kernel(const float* __restrict__ x,
                                                    const int* __restrict__ grid_sizes,
                                                    float* __restrict__ out) {
    int tid = threadIdx.x;                 // 0..63
    // Row = blockIdx.x: 1024 floats = 128 float8. Thread handles float8
    // slots tid and tid+64 (same d-offset group, heads h and h+8).
    long long base = (long long)blockIdx.x * 1024;
    const float* p0 = x + base + (long long)tid * 8;
    const float* p1 = p0 + 64 * 8;

    // ---- front-batch both 256-bit streaming loads (MLP_p1 = 2x32B) ----
    float v0[8], v1[8];
    ldg256_cs(p0, v0);
    ldg256_cs(p1, v1);

    // ---- position for this row ----
    unsigned row = blockIdx.x;
    unsigned s = row & ((1u << S_LOG2) - 1u);
    unsigned b = row >> S_LOG2;
    unsigned cols = (unsigned)__ldg(&grid_sizes[2 * b + 1]);
    unsigned i = s / cols;
    unsigned j = s - i * cols;
    float pos = (float)(i + j);

    // pairs k = 4u..4u+3 where u = tid & 7
    const float C = 13.287712379549449f / 32.0f;   // log2(10000)/32
    const float R = 0.7498942093324559f;           // 10000^(-1/32)
    int u = tid & 7;
    float th0 = exp2f(-(float)(4 * u) * C);
    float th1 = th0 * R;
    float th2 = th1 * R;
    float th3 = th2 * R;

    float c0, s0, c1, s1, c2, s2, c3, s3;
    __sincosf(pos * th0, &s0, &c0);
    __sincosf(pos * th1, &s1, &c1);
    __sincosf(pos * th2, &s2, &c2);
    __sincosf(pos * th3, &s3, &c3);

    float o0[8], o1[8];
#define ROT(o, v, idx, cc, ss)                                \
    do {                                                      \
        (o)[2*(idx)]   = fmaf((v)[2*(idx)],   cc, -(v)[2*(idx)+1] * ss); \
        (o)[2*(idx)+1] = fmaf((v)[2*(idx)+1], cc,  (v)[2*(idx)]   * ss); \
    } while (0)

    ROT(o0, v0, 0, c0, s0);
    ROT(o0, v0, 1, c1, s1);
    ROT(o0, v0, 2, c2, s2);
    ROT(o0, v0, 3, c3, s3);

    ROT(o1, v1, 0, c0, s0);
    ROT(o1, v1, 1, c1, s1);
    ROT(o1, v1, 2, c2, s2);
    ROT(o1, v1, 3, c3, s3);
#undef ROT

    float* q0 = out + base + (long long)tid * 8;
    float* q1 = q0 + 64 * 8;
    stg256_cs(q0, o0);
    stg256_cs(q1, o1);
}

extern "C" void kernel_launch(void* const* d_in, const int* in_sizes, int n_in,
                              void* d_out, int out_size) {
    const float* x = (const float*)d_in[0];
    const int* grid_sizes = (const int*)d_in[1];
    float* out = (float*)d_out;

    int nrows = in_sizes[0] / 1024;          // 32768 rows (B*S)
    rope2d_kernel<<<nrows, 64>>>(x, grid_sizes, out);
}

// round 14
// speedup vs baseline: 1.0221x; 1.0221x over previous
#include <cuda_runtime.h>
#include <math.h>

// RoPE-2D: x[B=32, S=1024, H=16, D=64] fp32, grid_sizes[B,2] int32.
// Combined rotation: rot(i*th) ∘ rot(j*th) == rot((i+j)*th)  -> one
// {cos,sin} pair per rotation pair instead of two gathers + 8 FMAs.
//
// FINAL (best measured, R11): one-shot grid, block=64 covering ONE s-row,
// 4 float4/thread front-batched with __ldcs; __stcs evict-first stores
// (measured better than .wb, which steals L2 fill slots from the read
// stream). All 4 vectors of a thread share one pos -> 2 sincos/thread,
// fully hidden under DRAM latency (issue ~17%).
// Runs at ~94% of the 8 TB/s HBM spec on the mandatory 268 MB of traffic;
// v8 ld/st, higher MLP, persistent CTAs, smem tables all measured neutral
// or worse. This is the streaming floor for this op on GB300.

#define F4_PER_ROW 16        // D=64 floats = 16 float4
#define S_LOG2 10

__global__ void __launch_bounds__(64) rope2d_kernel(const float4* __restrict__ x,
                                                    const int* __restrict__ grid_sizes,
                                                    float4* __restrict__ out) {
    int tid = threadIdx.x;                 // 0..63
    int f0 = blockIdx.x * 256 + tid;
    // Block covers one s-row = 256 float4. Thread handles
    // f0, f0+64, f0+128, f0+192 (same (b,s), same t, different heads).

    // ---- front-batch the 4 streaming loads (MLP_p1 = 4) ----
    float4 v0 = __ldcs(&x[f0]);
    float4 v1 = __ldcs(&x[f0 + 64]);
    float4 v2 = __ldcs(&x[f0 + 128]);
    float4 v3 = __ldcs(&x[f0 + 192]);

    // ---- position for this row ----
    unsigned row = blockIdx.x;
    unsigned s = row & ((1u << S_LOG2) - 1u);
    unsigned b = row >> S_LOG2;
    unsigned cols = (unsigned)__ldg(&grid_sizes[2 * b + 1]);
    unsigned i = s / cols;
    unsigned j = s - i * cols;
    int pos = (int)(i + j);

    // theta_k = 10000^(-k/32) = exp2(-k * log2(10000)/32)
    int t = tid & (F4_PER_ROW - 1);        // pairs k=2t, 2t+1
    const float C = 13.287712379549449f / 32.0f;   // log2(10000)/32
    const float R = 0.7498942093324559f;           // 10000^(-1/32)
    float th0 = exp2f(-(float)(2 * t) * C);
    float th1 = th0 * R;

    float ca, sa, cb, sb;
    __sincosf((float)pos * th0, &sa, &ca);
    __sincosf((float)pos * th1, &sb, &cb);

    float4 o0, o1, o2, o3;
    o0.x = fmaf(v0.x, ca, -v0.y * sa);
    o0.y = fmaf(v0.y, ca,  v0.x * sa);
    o0.z = fmaf(v0.z, cb, -v0.w * sb);
    o0.w = fmaf(v0.w, cb,  v0.z * sb);

    o1.x = fmaf(v1.x, ca, -v1.y * sa);
    o1.y = fmaf(v1.y, ca,  v1.x * sa);
    o1.z = fmaf(v1.z, cb, -v1.w * sb);
    o1.w = fmaf(v1.w, cb,  v1.z * sb);

    o2.x = fmaf(v2.x, ca, -v2.y * sa);
    o2.y = fmaf(v2.y, ca,  v2.x * sa);
    o2.z = fmaf(v2.z, cb, -v2.w * sb);
    o2.w = fmaf(v2.w, cb,  v2.z * sb);

    o3.x = fmaf(v3.x, ca, -v3.y * sa);
    o3.y = fmaf(v3.y, ca,  v3.x * sa);
    o3.z = fmaf(v3.z, cb, -v3.w * sb);
    o3.w = fmaf(v3.w, cb,  v3.z * sb);

    __stcs(&out[f0],       o0);
    __stcs(&out[f0 + 64],  o1);
    __stcs(&out[f0 + 128], o2);
    __stcs(&out[f0 + 192], o3);
}

extern "C" void kernel_launch(void* const* d_in, const int* in_sizes, int n_in,
                              void* d_out, int out_size) {
    const float4* x = (const float4*)d_in[0];
    const int* grid_sizes = (const int*)d_in[1];
    float4* out = (float4*)d_out;

    int total4 = in_sizes[0] / 4;            // 8,388,608 float4
    int nblocks = total4 / 256;              // 32768 blocks of 64 threads
    rope2d_kernel<<<nblocks, 64>>>(x, grid_sizes, out);
}

// round 15
// speedup vs baseline: 1.0228x; 1.0007x over previous
#include <cuda_runtime.h>
#include <math.h>

// RoPE-2D: x[B=32, S=1024, H=16, D=64] fp32, grid_sizes[B,2] int32.
// Combined rotation: rot(i*th) ∘ rot(j*th) == rot((i+j)*th).
//
// Experiment: MLP=8 at block=64 (2 rows / 512 float4 per block).
// R5 showed MLP=8 fails at block=256 via register-file occupancy
// (40 regs x 256 thr -> 62% occ). At block=64 the same reg count
// permits ~23 CTAs/SM (~72% occ) with doubled per-warp queue depth.
// Loads front-batched; rotate+store in consumption order (row0 fully
// retired before row1's sincos) to cap live registers.

#define F4_PER_ROW 16        // D=64 floats = 16 float4
#define S_LOG2 10

__global__ void __launch_bounds__(64) rope2d_kernel(const float4* __restrict__ x,
                                                    const int* __restrict__ grid_sizes,
                                                    float4* __restrict__ out) {
    int tid = threadIdx.x;                 // 0..63
    int f0 = blockIdx.x * 512 + tid;
    // Block covers 2 s-rows = 512 float4. Thread handles
    // f0+{0,64,128,192} (row0) and f0+{256,320,384,448} (row1).

    // ---- front-batch all 8 streaming loads (MLP_p1 = 8) ----
    float4 v0 = __ldcs(&x[f0]);
    float4 v1 = __ldcs(&x[f0 + 64]);
    float4 v2 = __ldcs(&x[f0 + 128]);
    float4 v3 = __ldcs(&x[f0 + 192]);
    float4 v4 = __ldcs(&x[f0 + 256]);
    float4 v5 = __ldcs(&x[f0 + 320]);
    float4 v6 = __ldcs(&x[f0 + 384]);
    float4 v7 = __ldcs(&x[f0 + 448]);

    // ---- positions for the 2 consecutive s-rows (same b, same cols) ----
    unsigned row0 = blockIdx.x * 2;
    unsigned s = row0 & ((1u << S_LOG2) - 1u);
    unsigned b = row0 >> S_LOG2;
    unsigned cols = (unsigned)__ldg(&grid_sizes[2 * b + 1]);
    unsigned i = s / cols;                 // one division for both rows
    unsigned j = s - i * cols;
    int pos0 = (int)(i + j);
    int pos1 = (j + 1u < cols) ? pos0 + 1 : (int)(i + 1u);

    // theta_k = 10000^(-k/32) = exp2(-k * log2(10000)/32)
    int t = tid & (F4_PER_ROW - 1);        // pairs k=2t, 2t+1
    const float C = 13.287712379549449f / 32.0f;   // log2(10000)/32
    const float R = 0.7498942093324559f;           // 10000^(-1/32)
    float th0 = exp2f(-(float)(2 * t) * C);
    float th1 = th0 * R;

#define ROT_ST(v, off, cc0, ss0, cc1, ss1)                    \
    do {                                                      \
        float4 o;                                             \
        o.x = fmaf((v).x, cc0, -(v).y * ss0);                 \
        o.y = fmaf((v).y, cc0,  (v).x * ss0);                 \
        o.z = fmaf((v).z, cc1, -(v).w * ss1);                 \
        o.w = fmaf((v).w, cc1,  (v).z * ss1);                 \
        __stcs(&out[f0 + (off)], o);                          \
    } while (0)

    // ---- row0: sincos, rotate, store (retire v0..v3 early) ----
    {
        float ca, sa, cb, sb;
        __sincosf((float)pos0 * th0, &sa, &ca);
        __sincosf((float)pos0 * th1, &sb, &cb);
        ROT_ST(v0, 0,   ca, sa, cb, sb);
        ROT_ST(v1, 64,  ca, sa, cb, sb);
        ROT_ST(v2, 128, ca, sa, cb, sb);
        ROT_ST(v3, 192, ca, sa, cb, sb);
    }

    // ---- row1 ----
    {
        float ca, sa, cb, sb;
        __sincosf((float)pos1 * th0, &sa, &ca);
        __sincosf((float)pos1 * th1, &sb, &cb);
        ROT_ST(v4, 256, ca, sa, cb, sb);
        ROT_ST(v5, 320, ca, sa, cb, sb);
        ROT_ST(v6, 384, ca, sa, cb, sb);
        ROT_ST(v7, 448, ca, sa, cb, sb);
    }
#undef ROT_ST
}

extern "C" void kernel_launch(void* const* d_in, const int* in_sizes, int n_in,
                              void* d_out, int out_size) {
    const float4* x = (const float4*)d_in[0];
    const int* grid_sizes = (const int*)d_in[1];
    float4* out = (float4*)d_out;

    int total4 = in_sizes[0] / 4;            // 8,388,608 float4
    int nblocks = total4 / 512;              // 16384 blocks of 64 threads
    rope2d_kernel<<<nblocks, 64>>>(x, grid_sizes, out);
}